// round 12
// baseline (speedup 1.0000x reference)
#include <cuda_runtime.h>
#include <cuda_fp16.h>
#include <cuda_bf16.h>
#include <cstdint>

#define NN 100000
#define NE 3200000
#define MP 100096   // 782 * 128 (padded rows)

// ================= scratch =================
__device__ uint16_t g_act[(size_t)MP * 256];    // fp16 activations (layers 2-4 input)
__device__ uint16_t g_suph[(size_t)MP * 256];   // fp16 support (GEMM out)
__device__ uint16_t g_wh[180224];               // fp16 Wt (all layers)
__device__ int   g_rowptr[NN + 1];
__device__ int   g_cursor[NN];
__device__ int   g_esrc[NE];
__device__ float g_ew[NE];

// ================= CSR build =================
__global__ void zero_counts_kernel() {
    int i = blockIdx.x * blockDim.x + threadIdx.x;
    if (i < NN) g_cursor[i] = 0;
}
// 4 edges per thread (int4 loads)
__global__ void hist_kernel(const int4* __restrict__ dst4) {
    int i = blockIdx.x * blockDim.x + threadIdx.x;
    if (i < NE / 4) {
        int4 d = dst4[i];
        atomicAdd(&g_cursor[d.x], 1);
        atomicAdd(&g_cursor[d.y], 1);
        atomicAdd(&g_cursor[d.z], 1);
        atomicAdd(&g_cursor[d.w], 1);
    }
}
__global__ void scan_kernel() {
    __shared__ int sdata[1024];
    const int T = 1024;
    const int CH = (NN + T - 1) / T;
    int t = threadIdx.x;
    int base = t * CH;
    int s = 0;
    for (int i = 0; i < CH; i++) { int idx = base + i; if (idx < NN) s += g_cursor[idx]; }
    sdata[t] = s;
    __syncthreads();
    for (int off = 1; off < T; off <<= 1) {
        int v = (t >= off) ? sdata[t - off] : 0;
        __syncthreads(); sdata[t] += v; __syncthreads();
    }
    int running = sdata[t] - s;
    for (int i = 0; i < CH; i++) {
        int idx = base + i;
        if (idx < NN) {
            int c = g_cursor[idx];
            g_rowptr[idx] = running;
            g_cursor[idx] = running;
            running += c;
        }
    }
    if (t == 0) g_rowptr[NN] = NE;
}
// 4 edges per thread (int4/float4 loads)
__global__ void scatter_kernel(const int4* __restrict__ src4, const int4* __restrict__ dst4,
                               const float4* __restrict__ ew4) {
    int i = blockIdx.x * blockDim.x + threadIdx.x;
    if (i < NE / 4) {
        int4 s = src4[i];
        int4 d = dst4[i];
        float4 w = ew4[i];
        int p0 = atomicAdd(&g_cursor[d.x], 1);
        int p1 = atomicAdd(&g_cursor[d.y], 1);
        int p2 = atomicAdd(&g_cursor[d.z], 1);
        int p3 = atomicAdd(&g_cursor[d.w], 1);
        g_esrc[p0] = s.x; g_ew[p0] = w.x;
        g_esrc[p1] = s.y; g_ew[p1] = w.y;
        g_esrc[p2] = s.z; g_ew[p2] = w.z;
        g_esrc[p3] = s.w; g_ew[p3] = w.w;
    }
}

// ===== combined weight transpose+convert: W[K,N] fp32 -> Wt[NPr,K] fp16, all 4 layers =====
__global__ void split_w_all(const float* __restrict__ W1, const float* __restrict__ W2,
                            const float* __restrict__ W3, const float* __restrict__ W4) {
    int i = blockIdx.x * blockDim.x + threadIdx.x;
    if (i >= 176128) return;
    const float* W; int K, N, off;
    if (i < 131072)      { W = W1; K = 512; N = 256; off = 0; }
    else if (i < 163840) { W = W2; K = 256; N = 128; off = 131072; }
    else if (i < 172032) { W = W3; K = 128; N = 64;  off = 163840; }
    else                 { W = W4; K = 64;  N = 40;  off = 172032; }
    int local = i - off;
    int n = local / K, k = local % K;
    float v = (n < N) ? W[(size_t)k * N + n] : 0.f;
    g_wh[i] = __half_raw(__float2half_rn(v)).x;
}

// ================= mma.sync / cp.async helpers =================
__device__ __forceinline__ uint32_t smem_u32(const void* p) {
    uint32_t a;
    asm("{ .reg .u64 t; cvta.to.shared.u64 t, %1; cvt.u32.u64 %0, t; }" : "=r"(a) : "l"(p));
    return a;
}
__device__ __forceinline__ void ldsm_x4(uint32_t* r, uint32_t addr) {
    asm volatile("ldmatrix.sync.aligned.m8n8.x4.shared.b16 {%0,%1,%2,%3}, [%4];"
                 : "=r"(r[0]), "=r"(r[1]), "=r"(r[2]), "=r"(r[3]) : "r"(addr));
}
__device__ __forceinline__ void ldsm_x2(uint32_t* r, uint32_t addr) {
    asm volatile("ldmatrix.sync.aligned.m8n8.x2.shared.b16 {%0,%1}, [%2];"
                 : "=r"(r[0]), "=r"(r[1]) : "r"(addr));
}
__device__ __forceinline__ void mma_f16(float* c, const uint32_t* a, const uint32_t* b) {
    asm volatile(
        "mma.sync.aligned.m16n8k16.row.col.f32.f16.f16.f32 "
        "{%0,%1,%2,%3}, {%4,%5,%6,%7}, {%8,%9}, {%0,%1,%2,%3};"
        : "+f"(c[0]), "+f"(c[1]), "+f"(c[2]), "+f"(c[3])
        : "r"(a[0]), "r"(a[1]), "r"(a[2]), "r"(a[3]), "r"(b[0]), "r"(b[1]));
}
__device__ __forceinline__ void cp16(uint32_t saddr, const void* gptr) {
    asm volatile("cp.async.cg.shared.global [%0], [%1], 16;" :: "r"(saddr), "l"(gptr));
}
__device__ __forceinline__ void cp_commit() { asm volatile("cp.async.commit_group;"); }
template <int N>
__device__ __forceinline__ void cp_wait() { asm volatile("cp.async.wait_group %0;" :: "n"(N)); }

// ---- unified stage layout (all layers, 1-term): A 16K | B 8K ----
#define G1_STAGE 24576
#define G1_OFF_A 0
#define G1_OFF_B 16384

#define GEMM_COMPUTE_1T(stb)                                                               \
    do {                                                                                   \
        _Pragma("unroll")                                                                  \
        for (int ks = 0; ks < 4; ++ks) {                                                   \
            uint32_t ah[4][4], bh[2][2];                                                   \
            _Pragma("unroll")                                                              \
            for (int mf = 0; mf < 4; ++mf) {                                               \
                int r = wm + mf * 16 + a_row_l;                                            \
                uint32_t so = r * 128 + (((ks * 2 + a_chl) ^ (r & 7)) << 4);               \
                ldsm_x4(ah[mf], (stb) + G1_OFF_A + so);                                    \
            }                                                                              \
            _Pragma("unroll")                                                              \
            for (int nf = 0; nf < 2; ++nf) {                                               \
                int r = wn + nf * 8 + b_row_l;                                             \
                uint32_t so = r * 128 + (((ks * 2 + b_chl) ^ (r & 7)) << 4);               \
                ldsm_x2(bh[nf], (stb) + G1_OFF_B + so);                                    \
            }                                                                              \
            _Pragma("unroll")                                                              \
            for (int mf = 0; mf < 4; ++mf)                                                 \
                _Pragma("unroll")                                                          \
                for (int nf = 0; nf < 2; ++nf)                                             \
                    mma_f16(acc[mf][nf], ah[mf], bh[nf]);                                  \
        }                                                                                  \
    } while (0)

#define GEMM_EPILOGUE(NOUT)                                                                \
    do {                                                                                   \
        const int gid = lane >> 2, tid4 = lane & 3;                                        \
        _Pragma("unroll")                                                                  \
        for (int mf = 0; mf < 4; ++mf) {                                                   \
            _Pragma("unroll")                                                              \
            for (int nf = 0; nf < 2; ++nf) {                                               \
                int col = nb0 + wn + nf * 8 + tid4 * 2;                                    \
                if (col < (NOUT)) {                                                        \
                    int m0 = row0 + wm + mf * 16 + gid;                                    \
                    __half2 h0 = __floats2half2_rn(acc[mf][nf][0], acc[mf][nf][1]);        \
                    __half2 h1 = __floats2half2_rn(acc[mf][nf][2], acc[mf][nf][3]);        \
                    *(__half2*)(sup + (size_t)m0 * (NOUT) + col) = h0;                     \
                    *(__half2*)(sup + (size_t)(m0 + 8) * (NOUT) + col) = h1;               \
                }                                                                          \
            }                                                                              \
        }                                                                                  \
    } while (0)

// ================= layers 2-4 HMMA GEMM: single-term fp16 A =================
__global__ __launch_bounds__(256)
void gemm_hmma_kernel(const uint16_t* __restrict__ A,
                      const uint16_t* __restrict__ Bh,
                      __half* __restrict__ sup, int K, int NOUT) {
    extern __shared__ __align__(128) char smem[];
    const uint32_t sb = smem_u32(smem);
    const int tid = threadIdx.x, wid = tid >> 5, lane = tid & 31;
    const int row0 = blockIdx.y * 128;
    const int nb0 = blockIdx.x * 64;
    const int wm = (wid & 1) * 64;
    const int wn = (wid >> 1) * 16;

    float acc[4][2][4];
#pragma unroll
    for (int i = 0; i < 4; i++)
#pragma unroll
        for (int j = 0; j < 2; j++)
#pragma unroll
            for (int q = 0; q < 4; q++) acc[i][j][q] = 0.f;

    const int a_row_l = lane & 15;
    const int a_chl = lane >> 4;
    const int b_row_l = lane & 7;
    const int b_chl = (lane >> 3) & 1;
    const int CH = K >> 6;

    auto load_stage = [&](int c, int buf) {
        const int kbase = c * 64;
        const uint32_t so_base = sb + buf * G1_STAGE;
#pragma unroll
        for (int i = tid; i < 1024; i += 256) {
            int r = i >> 3, cb = i & 7;
            size_t gidx = (size_t)(row0 + r) * K + kbase + cb * 8;
            uint32_t so = r * 128 + ((cb ^ (r & 7)) << 4);
            cp16(so_base + G1_OFF_A + so, A + gidx);
        }
#pragma unroll
        for (int i = tid; i < 512; i += 256) {
            int r = i >> 3, cb = i & 7;
            size_t gidx = (size_t)r * K + kbase + cb * 8;
            uint32_t so = r * 128 + ((cb ^ (r & 7)) << 4);
            cp16(so_base + G1_OFF_B + so, Bh + (size_t)nb0 * K + gidx);
        }
        cp_commit();
    };

    load_stage(0, 0);
    for (int c = 0; c < CH; ++c) {
        if (c + 1 < CH) { load_stage(c + 1, (c + 1) & 1); cp_wait<1>(); }
        else cp_wait<0>();
        __syncthreads();
        const uint32_t stb = sb + (c & 1) * G1_STAGE;
        GEMM_COMPUTE_1T(stb);
        __syncthreads();
    }
    GEMM_EPILOGUE(NOUT);
}

// ====== layer-1 GEMM: fused fp32->fp16 convert of x (single term) ======
__global__ __launch_bounds__(256)
void gemm_l1_kernel(const float* __restrict__ x,
                    const uint16_t* __restrict__ Bh,
                    __half* __restrict__ sup) {
    extern __shared__ __align__(128) char smem[];
    const uint32_t sb = smem_u32(smem);
    const int tid = threadIdx.x, wid = tid >> 5, lane = tid & 31;
    const int row0 = blockIdx.y * 128;
    const int nb0 = blockIdx.x * 64;
    const int wm = (wid & 1) * 64;
    const int wn = (wid >> 1) * 16;
    const int K = 512, NOUT = 256, CH = 8;

    float acc[4][2][4];
#pragma unroll
    for (int i = 0; i < 4; i++)
#pragma unroll
        for (int j = 0; j < 2; j++)
#pragma unroll
            for (int q = 0; q < 4; q++) acc[i][j][q] = 0.f;

    const int a_row_l = lane & 15;
    const int a_chl = lane >> 4;
    const int b_row_l = lane & 7;
    const int b_chl = (lane >> 3) & 1;

    float4 areg[4][2];

    auto load_a = [&](int c) {
        const int kbase = c * 64;
#pragma unroll
        for (int it = 0; it < 4; it++) {
            int i = tid + it * 256;
            int r = i >> 3, cb = i & 7;
            int grow = row0 + r;
            if (grow < NN) {
                const float* gp = x + (size_t)grow * K + kbase + cb * 8;
                areg[it][0] = *(const float4*)gp;
                areg[it][1] = *(const float4*)(gp + 4);
            } else {
                areg[it][0] = make_float4(0.f, 0.f, 0.f, 0.f);
                areg[it][1] = make_float4(0.f, 0.f, 0.f, 0.f);
            }
        }
    };
    auto store_a = [&](int buf) {
#pragma unroll
        for (int it = 0; it < 4; it++) {
            int i = tid + it * 256;
            int r = i >> 3, cb = i & 7;
            uint32_t so = r * 128 + ((cb ^ (r & 7)) << 4);
            __half2 p0 = __floats2half2_rn(areg[it][0].x, areg[it][0].y);
            __half2 p1 = __floats2half2_rn(areg[it][0].z, areg[it][0].w);
            __half2 p2 = __floats2half2_rn(areg[it][1].x, areg[it][1].y);
            __half2 p3 = __floats2half2_rn(areg[it][1].z, areg[it][1].w);
            *(uint4*)(smem + buf * G1_STAGE + G1_OFF_A + so) =
                make_uint4(*(uint32_t*)&p0, *(uint32_t*)&p1, *(uint32_t*)&p2, *(uint32_t*)&p3);
        }
    };
    auto load_b = [&](int c, int buf) {
        const int kbase = c * 64;
        const uint32_t so_base = sb + buf * G1_STAGE;
#pragma unroll
        for (int i = tid; i < 512; i += 256) {
            int r = i >> 3, cb = i & 7;
            size_t gidx = (size_t)(nb0 + r) * K + kbase + cb * 8;
            uint32_t so = r * 128 + ((cb ^ (r & 7)) << 4);
            cp16(so_base + G1_OFF_B + so, Bh + gidx);
        }
        cp_commit();
    };

    load_a(0);
    load_b(0, 0);
    store_a(0);
    cp_wait<0>();
    __syncthreads();

    for (int c = 0; c < CH; ++c) {
        if (c + 1 < CH) { load_a(c + 1); load_b(c + 1, (c + 1) & 1); }
        const uint32_t stb = sb + (c & 1) * G1_STAGE;
        GEMM_COMPUTE_1T(stb);
        if (c + 1 < CH) {
            store_a((c + 1) & 1);
            cp_wait<0>();
            __syncthreads();
        }
    }
    GEMM_EPILOGUE(NOUT);
}

// ====== SpMM gather (fp16 support, 16B/lane, x4 edge unroll), fp16 act out ======
template <int D>
__global__ void spmm_vec_kernel(const __half* __restrict__ sup, const float* __restrict__ bias,
                                __half* __restrict__ act) {
    constexpr int LPE = D / 8;
    constexpr int EPI = 32 / LPE;
    const int warp = (blockIdx.x * blockDim.x + threadIdx.x) >> 5;
    const int lane = threadIdx.x & 31;
    if (warp >= NN) return;
    const int sub = lane / LPE;
    const int seg = lane % LPE;

    float acc[8];
#pragma unroll
    for (int q = 0; q < 8; q++) acc[q] = 0.f;

    const int e0 = g_rowptr[warp];
    const int e1 = g_rowptr[warp + 1];
    int e = e0;
    for (; e + 4 * EPI <= e1; e += 4 * EPI) {
        int s[4]; float w[4]; uint4 v[4];
#pragma unroll
        for (int u = 0; u < 4; u++) {
            int me = e + u * EPI + sub;
            s[u] = g_esrc[me];
            w[u] = g_ew[me];
        }
#pragma unroll
        for (int u = 0; u < 4; u++)
            v[u] = *((const uint4*)(sup + (size_t)s[u] * D) + seg);
#pragma unroll
        for (int u = 0; u < 4; u++) {
            float2 f0 = __half22float2(*(__half2*)&v[u].x);
            float2 f1 = __half22float2(*(__half2*)&v[u].y);
            float2 f2 = __half22float2(*(__half2*)&v[u].z);
            float2 f3 = __half22float2(*(__half2*)&v[u].w);
            acc[0] += w[u] * f0.x; acc[1] += w[u] * f0.y;
            acc[2] += w[u] * f1.x; acc[3] += w[u] * f1.y;
            acc[4] += w[u] * f2.x; acc[5] += w[u] * f2.y;
            acc[6] += w[u] * f3.x; acc[7] += w[u] * f3.y;
        }
    }
    for (; e < e1; e += EPI) {
        int me = e + sub;
        if (me < e1) {
            int s = g_esrc[me];
            float w = g_ew[me];
            uint4 v = *((const uint4*)(sup + (size_t)s * D) + seg);
            float2 f0 = __half22float2(*(__half2*)&v.x);
            float2 f1 = __half22float2(*(__half2*)&v.y);
            float2 f2 = __half22float2(*(__half2*)&v.z);
            float2 f3 = __half22float2(*(__half2*)&v.w);
            acc[0] += w * f0.x; acc[1] += w * f0.y;
            acc[2] += w * f1.x; acc[3] += w * f1.y;
            acc[4] += w * f2.x; acc[5] += w * f2.y;
            acc[6] += w * f3.x; acc[7] += w * f3.y;
        }
    }
#pragma unroll
    for (int off = LPE; off < 32; off <<= 1)
#pragma unroll
        for (int q = 0; q < 8; q++)
            acc[q] += __shfl_xor_sync(0xFFFFFFFFu, acc[q], off);

    if (lane < LPE) {
        int col0 = lane * 8;
        uint32_t p[4];
#pragma unroll
        for (int q = 0; q < 8; q += 2) {
            float vx = fmaxf(acc[q] + bias[col0 + q], 0.f);
            float vy = fmaxf(acc[q + 1] + bias[col0 + q + 1], 0.f);
            __half2 h2 = __floats2half2_rn(vx, vy);
            p[q >> 1] = *(uint32_t*)&h2;
        }
        *(uint4*)(act + (size_t)warp * D + col0) = make_uint4(p[0], p[1], p[2], p[3]);
    }
}

// ======== last layer: SpMM (D=40) fused with relu + log-softmax -> d_out =========
__global__ void spmm_lsm_kernel(const __half* __restrict__ sup, const float* __restrict__ bias,
                                float* __restrict__ out) {
    const int warp = (blockIdx.x * blockDim.x + threadIdx.x) >> 5;
    const int lane = threadIdx.x & 31;
    if (warp >= NN) return;
    float ax = 0.f, ay = 0.f;
    const int e0 = g_rowptr[warp];
    const int e1 = g_rowptr[warp + 1];
    const bool act = lane < 20;
    int e = e0;
    for (; e + 4 <= e1; e += 4) {
        int s[4]; float w[4]; float2 f[4];
#pragma unroll
        for (int u = 0; u < 4; u++) { s[u] = g_esrc[e + u]; w[u] = g_ew[e + u]; }
#pragma unroll
        for (int u = 0; u < 4; u++)
            f[u] = act ? __half22float2(((const __half2*)(sup + (size_t)s[u] * 40))[lane])
                       : make_float2(0.f, 0.f);
#pragma unroll
        for (int u = 0; u < 4; u++) { ax += w[u] * f[u].x; ay += w[u] * f[u].y; }
    }
    for (; e < e1; e++) {
        int s = g_esrc[e];
        float w = g_ew[e];
        if (act) {
            float2 f = __half22float2(((const __half2*)(sup + (size_t)s * 40))[lane]);
            ax += w * f.x; ay += w * f.y;
        }
    }
    float vx = act ? fmaxf(ax + bias[2 * lane], 0.f) : -INFINITY;
    float vy = act ? fmaxf(ay + bias[2 * lane + 1], 0.f) : -INFINITY;
    float m = fmaxf(vx, vy);
#pragma unroll
    for (int off = 16; off > 0; off >>= 1)
        m = fmaxf(m, __shfl_xor_sync(0xFFFFFFFFu, m, off));
    float s = act ? (expf(vx - m) + expf(vy - m)) : 0.f;
#pragma unroll
    for (int off = 16; off > 0; off >>= 1)
        s += __shfl_xor_sync(0xFFFFFFFFu, s, off);
    float lse = logf(s) + m;
    if (act) {
        out[(size_t)warp * 40 + 2 * lane] = vx - lse;
        out[(size_t)warp * 40 + 2 * lane + 1] = vy - lse;
    }
}

// ================= launch =================
extern "C" void kernel_launch(void* const* d_in, const int* in_sizes, int n_in,
                              void* d_out, int out_size) {
    const float* x  = (const float*)d_in[0];
    const int* esrc = (const int*)d_in[1];
    const int* edst = (const int*)d_in[2];
    const float* ew = (const float*)d_in[3];
    const float* W1 = (const float*)d_in[4];
    const float* b1 = (const float*)d_in[5];
    const float* W2 = (const float*)d_in[6];
    const float* b2 = (const float*)d_in[7];
    const float* W3 = (const float*)d_in[8];
    const float* b3 = (const float*)d_in[9];
    const float* W4 = (const float*)d_in[10];
    const float* b4 = (const float*)d_in[11];
    float* out = (float*)d_out;

    uint16_t *act_u, *suph_u, *wh;
    cudaGetSymbolAddress((void**)&act_u, g_act);
    cudaGetSymbolAddress((void**)&suph_u, g_suph);
    cudaGetSymbolAddress((void**)&wh, g_wh);
    __half* act = (__half*)act_u;
    __half* suph = (__half*)suph_u;

    const int WOFF1 = 0, WOFF2 = 131072, WOFF3 = 163840, WOFF4 = 172032;

    cudaFuncSetAttribute(gemm_hmma_kernel, cudaFuncAttributeMaxDynamicSharedMemorySize, 2 * G1_STAGE);
    cudaFuncSetAttribute(gemm_l1_kernel, cudaFuncAttributeMaxDynamicSharedMemorySize, 2 * G1_STAGE);

    static cudaStream_t s2 = nullptr;
    static cudaEvent_t ev_fork = nullptr, ev_join = nullptr;
    if (!s2) {
        cudaStreamCreateWithFlags(&s2, cudaStreamNonBlocking);
        cudaEventCreateWithFlags(&ev_fork, cudaEventDisableTiming);
        cudaEventCreateWithFlags(&ev_join, cudaEventDisableTiming);
    }

    cudaEventRecord(ev_fork, 0);
    cudaStreamWaitEvent(s2, ev_fork, 0);
    zero_counts_kernel<<<(NN + 255) / 256, 256, 0, s2>>>();
    hist_kernel<<<(NE / 4 + 255) / 256, 256, 0, s2>>>((const int4*)edst);
    scan_kernel<<<1, 1024, 0, s2>>>();
    scatter_kernel<<<(NE / 4 + 255) / 256, 256, 0, s2>>>((const int4*)esrc, (const int4*)edst,
                                                         (const float4*)ew);
    cudaEventRecord(ev_join, s2);

    split_w_all<<<(176128 + 255) / 256, 256>>>(W1, W2, W3, W4);

    const int GY = MP / 128;  // 782
    const int SPMM_BLOCKS = (NN * 32 + 255) / 256;

    // Layer 1 (fused fp32->fp16 convert, 1-term): 512 -> 256
    gemm_l1_kernel<<<dim3(4, GY), 256, 2 * G1_STAGE>>>(x, wh + WOFF1, suph);
    cudaStreamWaitEvent(0, ev_join, 0);
    spmm_vec_kernel<256><<<SPMM_BLOCKS, 256>>>(suph, b1, act);

    gemm_hmma_kernel<<<dim3(2, GY), 256, 2 * G1_STAGE>>>(act_u, wh + WOFF2, suph, 256, 128);
    spmm_vec_kernel<128><<<SPMM_BLOCKS, 256>>>(suph, b2, act);

    gemm_hmma_kernel<<<dim3(1, GY), 256, 2 * G1_STAGE>>>(act_u, wh + WOFF3, suph, 128, 64);
    spmm_vec_kernel<64><<<SPMM_BLOCKS, 256>>>(suph, b3, act);

    gemm_hmma_kernel<<<dim3(1, GY), 256, 2 * G1_STAGE>>>(act_u, wh + WOFF4, suph, 64, 40);
    spmm_lsm_kernel<<<SPMM_BLOCKS, 256>>>(suph, b4, out);
}

// round 14
// speedup vs baseline: 1.1479x; 1.1479x over previous
#include <cuda_runtime.h>
#include <cuda_fp16.h>
#include <cuda_bf16.h>
#include <cstdint>

#define NN 100000
#define NE 3200000
#define MP 100096   // 782 * 128 (padded rows)

// ================= scratch =================
__device__ uint16_t g_act[(size_t)MP * 256];    // fp16 activations (layers 2-4 input)
__device__ uint16_t g_suph[(size_t)MP * 256];   // fp16 support (GEMM out)
__device__ uint16_t g_wh[180224];               // fp16 Wt (all layers)
__device__ int   g_rowptr[NN + 1];
__device__ int   g_cursor[NN];
__device__ int2  g_edge[NE];                    // packed (src, ew-bits)
__device__ uint16_t g_xh[(size_t)MP * 512];     // fp16 x (hi)
__device__ uint16_t g_xl[(size_t)MP * 512];     // fp16 x (lo) -- used by 2-term l1

// ================= CSR build =================
__global__ void zero_counts_kernel() {
    int i = blockIdx.x * blockDim.x + threadIdx.x;
    if (i < NN) g_cursor[i] = 0;
}
__global__ void hist_kernel(const int* __restrict__ dst) {
    int e = blockIdx.x * blockDim.x + threadIdx.x;
    if (e < NE) atomicAdd(&g_cursor[dst[e]], 1);
}
__global__ void scan_kernel() {
    __shared__ int sdata[1024];
    const int T = 1024;
    const int CH = (NN + T - 1) / T;
    int t = threadIdx.x;
    int base = t * CH;
    int s = 0;
    for (int i = 0; i < CH; i++) { int idx = base + i; if (idx < NN) s += g_cursor[idx]; }
    sdata[t] = s;
    __syncthreads();
    for (int off = 1; off < T; off <<= 1) {
        int v = (t >= off) ? sdata[t - off] : 0;
        __syncthreads(); sdata[t] += v; __syncthreads();
    }
    int running = sdata[t] - s;
    for (int i = 0; i < CH; i++) {
        int idx = base + i;
        if (idx < NN) {
            int c = g_cursor[idx];
            g_rowptr[idx] = running;
            g_cursor[idx] = running;
            running += c;
        }
    }
    if (t == 0) g_rowptr[NN] = NE;
}
__global__ void scatter_kernel(const int* __restrict__ src, const int* __restrict__ dst,
                               const float* __restrict__ ew) {
    int e = blockIdx.x * blockDim.x + threadIdx.x;
    if (e < NE) {
        int d = dst[e];
        int pos = atomicAdd(&g_cursor[d], 1);
        g_edge[pos] = make_int2(src[e], __float_as_int(ew[e]));
    }
}

// ================= fp16 split helpers =================
__device__ __forceinline__ void split2h(float f0, float f1, uint32_t& hi, uint32_t& lo) {
    __half h0 = __float2half_rn(f0), h1 = __float2half_rn(f1);
    float r0 = f0 - __half2float(h0), r1 = f1 - __half2float(h1);
    __half l0 = __float2half_rn(r0), l1 = __float2half_rn(r1);
    hi = (uint32_t)__half_raw(h0).x | ((uint32_t)__half_raw(h1).x << 16);
    lo = (uint32_t)__half_raw(l0).x | ((uint32_t)__half_raw(l1).x << 16);
}

// ===== combined weight transpose+convert: W[K,N] fp32 -> Wt[NPr,K] fp16, all 4 layers =====
__global__ void split_w_all(const float* __restrict__ W1, const float* __restrict__ W2,
                            const float* __restrict__ W3, const float* __restrict__ W4) {
    int i = blockIdx.x * blockDim.x + threadIdx.x;
    if (i >= 176128) return;
    const float* W; int K, N, off;
    if (i < 131072)      { W = W1; K = 512; N = 256; off = 0; }
    else if (i < 163840) { W = W2; K = 256; N = 128; off = 131072; }
    else if (i < 172032) { W = W3; K = 128; N = 64;  off = 163840; }
    else                 { W = W4; K = 64;  N = 40;  off = 172032; }
    int local = i - off;
    int n = local / K, k = local % K;
    float v = (n < N) ? W[(size_t)k * N + n] : 0.f;
    g_wh[i] = __half_raw(__float2half_rn(v)).x;
}

// ================= mma.sync / cp.async helpers =================
__device__ __forceinline__ uint32_t smem_u32(const void* p) {
    uint32_t a;
    asm("{ .reg .u64 t; cvta.to.shared.u64 t, %1; cvt.u32.u64 %0, t; }" : "=r"(a) : "l"(p));
    return a;
}
__device__ __forceinline__ void ldsm_x4(uint32_t* r, uint32_t addr) {
    asm volatile("ldmatrix.sync.aligned.m8n8.x4.shared.b16 {%0,%1,%2,%3}, [%4];"
                 : "=r"(r[0]), "=r"(r[1]), "=r"(r[2]), "=r"(r[3]) : "r"(addr));
}
__device__ __forceinline__ void ldsm_x2(uint32_t* r, uint32_t addr) {
    asm volatile("ldmatrix.sync.aligned.m8n8.x2.shared.b16 {%0,%1}, [%2];"
                 : "=r"(r[0]), "=r"(r[1]) : "r"(addr));
}
__device__ __forceinline__ void mma_f16(float* c, const uint32_t* a, const uint32_t* b) {
    asm volatile(
        "mma.sync.aligned.m16n8k16.row.col.f32.f16.f16.f32 "
        "{%0,%1,%2,%3}, {%4,%5,%6,%7}, {%8,%9}, {%0,%1,%2,%3};"
        : "+f"(c[0]), "+f"(c[1]), "+f"(c[2]), "+f"(c[3])
        : "r"(a[0]), "r"(a[1]), "r"(a[2]), "r"(a[3]), "r"(b[0]), "r"(b[1]));
}
__device__ __forceinline__ void cp16(uint32_t saddr, const void* gptr) {
    asm volatile("cp.async.cg.shared.global [%0], [%1], 16;" :: "r"(saddr), "l"(gptr));
}
__device__ __forceinline__ void cp_commit() { asm volatile("cp.async.commit_group;"); }
template <int N>
__device__ __forceinline__ void cp_wait() { asm volatile("cp.async.wait_group %0;" :: "n"(N)); }

// ---- layer-1 (2-term) stage layout: AH 16K | AL 16K | B 8K ----
#define L1_STAGE 40960
#define L1_OFF_AH 0
#define L1_OFF_AL 16384
#define L1_OFF_BH 32768
// ---- layers 2-4 (1-term) stage layout: A 16K | B 8K ----
#define G1_STAGE 24576
#define G1_OFF_A 0
#define G1_OFF_B 16384

#define GEMM_COMPUTE_1T(stb)                                                               \
    do {                                                                                   \
        _Pragma("unroll")                                                                  \
        for (int ks = 0; ks < 4; ++ks) {                                                   \
            uint32_t ah[4][4], bh[2][2];                                                   \
            _Pragma("unroll")                                                              \
            for (int mf = 0; mf < 4; ++mf) {                                               \
                int r = wm + mf * 16 + a_row_l;                                            \
                uint32_t so = r * 128 + (((ks * 2 + a_chl) ^ (r & 7)) << 4);               \
                ldsm_x4(ah[mf], (stb) + G1_OFF_A + so);                                    \
            }                                                                              \
            _Pragma("unroll")                                                              \
            for (int nf = 0; nf < 2; ++nf) {                                               \
                int r = wn + nf * 8 + b_row_l;                                             \
                uint32_t so = r * 128 + (((ks * 2 + b_chl) ^ (r & 7)) << 4);               \
                ldsm_x2(bh[nf], (stb) + G1_OFF_B + so);                                    \
            }                                                                              \
            _Pragma("unroll")                                                              \
            for (int mf = 0; mf < 4; ++mf)                                                 \
                _Pragma("unroll")                                                          \
                for (int nf = 0; nf < 2; ++nf)                                             \
                    mma_f16(acc[mf][nf], ah[mf], bh[nf]);                                  \
        }                                                                                  \
    } while (0)

#define GEMM_EPILOGUE(NOUT)                                                                \
    do {                                                                                   \
        const int gid = lane >> 2, tid4 = lane & 3;                                        \
        _Pragma("unroll")                                                                  \
        for (int mf = 0; mf < 4; ++mf) {                                                   \
            _Pragma("unroll")                                                              \
            for (int nf = 0; nf < 2; ++nf) {                                               \
                int col = nb0 + wn + nf * 8 + tid4 * 2;                                    \
                if (col < (NOUT)) {                                                        \
                    int m0 = row0 + wm + mf * 16 + gid;                                    \
                    __half2 h0 = __floats2half2_rn(acc[mf][nf][0], acc[mf][nf][1]);        \
                    __half2 h1 = __floats2half2_rn(acc[mf][nf][2], acc[mf][nf][3]);        \
                    *(__half2*)(sup + (size_t)m0 * (NOUT) + col) = h0;                     \
                    *(__half2*)(sup + (size_t)(m0 + 8) * (NOUT) + col) = h1;               \
                }                                                                          \
            }                                                                              \
        }                                                                                  \
    } while (0)

// ================= layers 2-4 HMMA GEMM: single-term fp16 A =================
__global__ __launch_bounds__(256)
void gemm_hmma_kernel(const uint16_t* __restrict__ A,
                      const uint16_t* __restrict__ Bh,
                      __half* __restrict__ sup, int K, int NOUT) {
    extern __shared__ __align__(128) char smem[];
    const uint32_t sb = smem_u32(smem);
    const int tid = threadIdx.x, wid = tid >> 5, lane = tid & 31;
    const int row0 = blockIdx.y * 128;
    const int nb0 = blockIdx.x * 64;
    const int wm = (wid & 1) * 64;
    const int wn = (wid >> 1) * 16;

    float acc[4][2][4];
#pragma unroll
    for (int i = 0; i < 4; i++)
#pragma unroll
        for (int j = 0; j < 2; j++)
#pragma unroll
            for (int q = 0; q < 4; q++) acc[i][j][q] = 0.f;

    const int a_row_l = lane & 15;
    const int a_chl = lane >> 4;
    const int b_row_l = lane & 7;
    const int b_chl = (lane >> 3) & 1;
    const int CH = K >> 6;

    auto load_stage = [&](int c, int buf) {
        const int kbase = c * 64;
        const uint32_t so_base = sb + buf * G1_STAGE;
#pragma unroll
        for (int i = tid; i < 1024; i += 256) {
            int r = i >> 3, cb = i & 7;
            size_t gidx = (size_t)(row0 + r) * K + kbase + cb * 8;
            uint32_t so = r * 128 + ((cb ^ (r & 7)) << 4);
            cp16(so_base + G1_OFF_A + so, A + gidx);
        }
#pragma unroll
        for (int i = tid; i < 512; i += 256) {
            int r = i >> 3, cb = i & 7;
            size_t gidx = (size_t)(nb0 + r) * K + kbase + cb * 8;
            uint32_t so = r * 128 + ((cb ^ (r & 7)) << 4);
            cp16(so_base + G1_OFF_B + so, Bh + gidx);
        }
        cp_commit();
    };

    load_stage(0, 0);
    for (int c = 0; c < CH; ++c) {
        if (c + 1 < CH) { load_stage(c + 1, (c + 1) & 1); cp_wait<1>(); }
        else cp_wait<0>();
        __syncthreads();
        const uint32_t stb = sb + (c & 1) * G1_STAGE;
        GEMM_COMPUTE_1T(stb);
        __syncthreads();
    }
    GEMM_EPILOGUE(NOUT);
}

// ====== layer-1 GEMM: fused fp32->fp16 hi/lo split of x (2-term, R11-proven) ======
__global__ __launch_bounds__(256)
void gemm_l1_kernel(const float* __restrict__ x,
                    const uint16_t* __restrict__ Bh,
                    __half* __restrict__ sup) {
    extern __shared__ __align__(128) char smem[];
    const uint32_t sb = smem_u32(smem);
    const int tid = threadIdx.x, wid = tid >> 5, lane = tid & 31;
    const int row0 = blockIdx.y * 128;
    const int nb0 = blockIdx.x * 64;
    const int wm = (wid & 1) * 64;
    const int wn = (wid >> 1) * 16;
    const int K = 512, NOUT = 256, CH = 8;

    float acc[4][2][4];
#pragma unroll
    for (int i = 0; i < 4; i++)
#pragma unroll
        for (int j = 0; j < 2; j++)
#pragma unroll
            for (int q = 0; q < 4; q++) acc[i][j][q] = 0.f;

    const int a_row_l = lane & 15;
    const int a_chl = lane >> 4;
    const int b_row_l = lane & 7;
    const int b_chl = (lane >> 3) & 1;

    float4 areg[4][2];

    auto load_a = [&](int c) {
        const int kbase = c * 64;
#pragma unroll
        for (int it = 0; it < 4; it++) {
            int i = tid + it * 256;
            int r = i >> 3, cb = i & 7;
            int grow = row0 + r;
            if (grow < NN) {
                const float* gp = x + (size_t)grow * K + kbase + cb * 8;
                areg[it][0] = *(const float4*)gp;
                areg[it][1] = *(const float4*)(gp + 4);
            } else {
                areg[it][0] = make_float4(0.f, 0.f, 0.f, 0.f);
                areg[it][1] = make_float4(0.f, 0.f, 0.f, 0.f);
            }
        }
    };
    auto store_a = [&](int buf) {
#pragma unroll
        for (int it = 0; it < 4; it++) {
            int i = tid + it * 256;
            int r = i >> 3, cb = i & 7;
            uint32_t so = r * 128 + ((cb ^ (r & 7)) << 4);
            float f[8] = {areg[it][0].x, areg[it][0].y, areg[it][0].z, areg[it][0].w,
                          areg[it][1].x, areg[it][1].y, areg[it][1].z, areg[it][1].w};
            uint32_t hi[4], lo[4];
#pragma unroll
            for (int q = 0; q < 4; q++) split2h(f[2 * q], f[2 * q + 1], hi[q], lo[q]);
            *(uint4*)(smem + buf * L1_STAGE + L1_OFF_AH + so) = make_uint4(hi[0], hi[1], hi[2], hi[3]);
            *(uint4*)(smem + buf * L1_STAGE + L1_OFF_AL + so) = make_uint4(lo[0], lo[1], lo[2], lo[3]);
        }
    };
    auto load_b = [&](int c, int buf) {
        const int kbase = c * 64;
        const uint32_t so_base = sb + buf * L1_STAGE;
#pragma unroll
        for (int i = tid; i < 512; i += 256) {
            int r = i >> 3, cb = i & 7;
            size_t gidx = (size_t)(nb0 + r) * K + kbase + cb * 8;
            uint32_t so = r * 128 + ((cb ^ (r & 7)) << 4);
            cp16(so_base + L1_OFF_BH + so, Bh + gidx);
        }
        cp_commit();
    };

    load_a(0);
    load_b(0, 0);
    store_a(0);
    cp_wait<0>();
    __syncthreads();

    for (int c = 0; c < CH; ++c) {
        if (c + 1 < CH) { load_a(c + 1); load_b(c + 1, (c + 1) & 1); }
        const uint32_t stb = sb + (c & 1) * L1_STAGE;
#pragma unroll
        for (int ks = 0; ks < 4; ++ks) {
            uint32_t ah[4][4], al[4][4], bh[2][2];
#pragma unroll
            for (int mf = 0; mf < 4; ++mf) {
                int r = wm + mf * 16 + a_row_l;
                uint32_t so = r * 128 + (((ks * 2 + a_chl) ^ (r & 7)) << 4);
                ldsm_x4(ah[mf], stb + L1_OFF_AH + so);
                ldsm_x4(al[mf], stb + L1_OFF_AL + so);
            }
#pragma unroll
            for (int nf = 0; nf < 2; ++nf) {
                int r = wn + nf * 8 + b_row_l;
                uint32_t so = r * 128 + (((ks * 2 + b_chl) ^ (r & 7)) << 4);
                ldsm_x2(bh[nf], stb + L1_OFF_BH + so);
            }
#pragma unroll
            for (int mf = 0; mf < 4; ++mf)
#pragma unroll
                for (int nf = 0; nf < 2; ++nf) {
                    mma_f16(acc[mf][nf], ah[mf], bh[nf]);
                    mma_f16(acc[mf][nf], al[mf], bh[nf]);
                }
        }
        if (c + 1 < CH) {
            store_a((c + 1) & 1);
            cp_wait<0>();
            __syncthreads();
        }
    }
    GEMM_EPILOGUE(NOUT);
}

// ====== SpMM gather (fp16 support, 16B/lane, x4 edge unroll, packed edges) ======
template <int D>
__global__ void spmm_vec_kernel(const __half* __restrict__ sup, const float* __restrict__ bias,
                                __half* __restrict__ act) {
    constexpr int LPE = D / 8;
    constexpr int EPI = 32 / LPE;
    const int warp = (blockIdx.x * blockDim.x + threadIdx.x) >> 5;
    const int lane = threadIdx.x & 31;
    if (warp >= NN) return;
    const int sub = lane / LPE;
    const int seg = lane % LPE;

    float acc[8];
#pragma unroll
    for (int q = 0; q < 8; q++) acc[q] = 0.f;

    const int e0 = g_rowptr[warp];
    const int e1 = g_rowptr[warp + 1];
    int e = e0;
    for (; e + 4 * EPI <= e1; e += 4 * EPI) {
        int2 ed[4]; uint4 v[4];
#pragma unroll
        for (int u = 0; u < 4; u++) ed[u] = g_edge[e + u * EPI + sub];
#pragma unroll
        for (int u = 0; u < 4; u++)
            v[u] = *((const uint4*)(sup + (size_t)ed[u].x * D) + seg);
#pragma unroll
        for (int u = 0; u < 4; u++) {
            float w = __int_as_float(ed[u].y);
            float2 f0 = __half22float2(*(__half2*)&v[u].x);
            float2 f1 = __half22float2(*(__half2*)&v[u].y);
            float2 f2 = __half22float2(*(__half2*)&v[u].z);
            float2 f3 = __half22float2(*(__half2*)&v[u].w);
            acc[0] += w * f0.x; acc[1] += w * f0.y;
            acc[2] += w * f1.x; acc[3] += w * f1.y;
            acc[4] += w * f2.x; acc[5] += w * f2.y;
            acc[6] += w * f3.x; acc[7] += w * f3.y;
        }
    }
    for (; e < e1; e += EPI) {
        int me = e + sub;
        if (me < e1) {
            int2 ed = g_edge[me];
            float w = __int_as_float(ed.y);
            uint4 v = *((const uint4*)(sup + (size_t)ed.x * D) + seg);
            float2 f0 = __half22float2(*(__half2*)&v.x);
            float2 f1 = __half22float2(*(__half2*)&v.y);
            float2 f2 = __half22float2(*(__half2*)&v.z);
            float2 f3 = __half22float2(*(__half2*)&v.w);
            acc[0] += w * f0.x; acc[1] += w * f0.y;
            acc[2] += w * f1.x; acc[3] += w * f1.y;
            acc[4] += w * f2.x; acc[5] += w * f2.y;
            acc[6] += w * f3.x; acc[7] += w * f3.y;
        }
    }
#pragma unroll
    for (int off = LPE; off < 32; off <<= 1)
#pragma unroll
        for (int q = 0; q < 8; q++)
            acc[q] += __shfl_xor_sync(0xFFFFFFFFu, acc[q], off);

    if (lane < LPE) {
        int col0 = lane * 8;
        uint32_t p[4];
#pragma unroll
        for (int q = 0; q < 8; q += 2) {
            float vx = fmaxf(acc[q] + bias[col0 + q], 0.f);
            float vy = fmaxf(acc[q + 1] + bias[col0 + q + 1], 0.f);
            __half2 h2 = __floats2half2_rn(vx, vy);
            p[q >> 1] = *(uint32_t*)&h2;
        }
        *(uint4*)(act + (size_t)warp * D + col0) = make_uint4(p[0], p[1], p[2], p[3]);
    }
}

// ======== last layer: SpMM (D=40) fused with relu + log-softmax -> d_out =========
__global__ void spmm_lsm_kernel(const __half* __restrict__ sup, const float* __restrict__ bias,
                                float* __restrict__ out) {
    const int warp = (blockIdx.x * blockDim.x + threadIdx.x) >> 5;
    const int lane = threadIdx.x & 31;
    if (warp >= NN) return;
    float ax = 0.f, ay = 0.f;
    const int e0 = g_rowptr[warp];
    const int e1 = g_rowptr[warp + 1];
    const bool act = lane < 20;
    int e = e0;
    for (; e + 4 <= e1; e += 4) {
        int2 ed[4]; float2 f[4];
#pragma unroll
        for (int u = 0; u < 4; u++) ed[u] = g_edge[e + u];
#pragma unroll
        for (int u = 0; u < 4; u++)
            f[u] = act ? __half22float2(((const __half2*)(sup + (size_t)ed[u].x * 40))[lane])
                       : make_float2(0.f, 0.f);
#pragma unroll
        for (int u = 0; u < 4; u++) {
            float w = __int_as_float(ed[u].y);
            ax += w * f[u].x; ay += w * f[u].y;
        }
    }
    for (; e < e1; e++) {
        int2 ed = g_edge[e];
        float w = __int_as_float(ed.y);
        if (act) {
            float2 f = __half22float2(((const __half2*)(sup + (size_t)ed.x * 40))[lane]);
            ax += w * f.x; ay += w * f.y;
        }
    }
    float vx = act ? fmaxf(ax + bias[2 * lane], 0.f) : -INFINITY;
    float vy = act ? fmaxf(ay + bias[2 * lane + 1], 0.f) : -INFINITY;
    float m = fmaxf(vx, vy);
#pragma unroll
    for (int off = 16; off > 0; off >>= 1)
        m = fmaxf(m, __shfl_xor_sync(0xFFFFFFFFu, m, off));
    float s = act ? (expf(vx - m) + expf(vy - m)) : 0.f;
#pragma unroll
    for (int off = 16; off > 0; off >>= 1)
        s += __shfl_xor_sync(0xFFFFFFFFu, s, off);
    float lse = logf(s) + m;
    if (act) {
        out[(size_t)warp * 40 + 2 * lane] = vx - lse;
        out[(size_t)warp * 40 + 2 * lane + 1] = vy - lse;
    }
}

// ================= launch =================
extern "C" void kernel_launch(void* const* d_in, const int* in_sizes, int n_in,
                              void* d_out, int out_size) {
    const float* x  = (const float*)d_in[0];
    const int* esrc = (const int*)d_in[1];
    const int* edst = (const int*)d_in[2];
    const float* ew = (const float*)d_in[3];
    const float* W1 = (const float*)d_in[4];
    const float* b1 = (const float*)d_in[5];
    const float* W2 = (const float*)d_in[6];
    const float* b2 = (const float*)d_in[7];
    const float* W3 = (const float*)d_in[8];
    const float* b3 = (const float*)d_in[9];
    const float* W4 = (const float*)d_in[10];
    const float* b4 = (const float*)d_in[11];
    float* out = (float*)d_out;

    uint16_t *act_u, *suph_u, *wh;
    cudaGetSymbolAddress((void**)&act_u, g_act);
    cudaGetSymbolAddress((void**)&suph_u, g_suph);
    cudaGetSymbolAddress((void**)&wh, g_wh);
    __half* act = (__half*)act_u;
    __half* suph = (__half*)suph_u;

    const int WOFF1 = 0, WOFF2 = 131072, WOFF3 = 163840, WOFF4 = 172032;

    cudaFuncSetAttribute(gemm_hmma_kernel, cudaFuncAttributeMaxDynamicSharedMemorySize, 2 * G1_STAGE);
    cudaFuncSetAttribute(gemm_l1_kernel, cudaFuncAttributeMaxDynamicSharedMemorySize, 2 * L1_STAGE);

    static cudaStream_t s2 = nullptr;
    static cudaEvent_t ev_fork = nullptr, ev_join = nullptr;
    if (!s2) {
        cudaStreamCreateWithFlags(&s2, cudaStreamNonBlocking);
        cudaEventCreateWithFlags(&ev_fork, cudaEventDisableTiming);
        cudaEventCreateWithFlags(&ev_join, cudaEventDisableTiming);
    }

    cudaEventRecord(ev_fork, 0);
    cudaStreamWaitEvent(s2, ev_fork, 0);
    zero_counts_kernel<<<(NN + 255) / 256, 256, 0, s2>>>();
    hist_kernel<<<(NE + 255) / 256, 256, 0, s2>>>(edst);
    scan_kernel<<<1, 1024, 0, s2>>>();
    scatter_kernel<<<(NE + 255) / 256, 256, 0, s2>>>(esrc, edst, ew);
    cudaEventRecord(ev_join, s2);

    split_w_all<<<(176128 + 255) / 256, 256>>>(W1, W2, W3, W4);

    const int GY = MP / 128;  // 782
    const int SPMM_BLOCKS = (NN * 32 + 255) / 256;

    // Layer 1 (fused fp32 split, 2-term): 512 -> 256
    gemm_l1_kernel<<<dim3(4, GY), 256, 2 * L1_STAGE>>>(x, wh + WOFF1, suph);
    cudaStreamWaitEvent(0, ev_join, 0);
    spmm_vec_kernel<256><<<SPMM_BLOCKS, 256>>>(suph, b1, act);

    gemm_hmma_kernel<<<dim3(2, GY), 256, 2 * G1_STAGE>>>(act_u, wh + WOFF2, suph, 256, 128);
    spmm_vec_kernel<128><<<SPMM_BLOCKS, 256>>>(suph, b2, act);

    gemm_hmma_kernel<<<dim3(1, GY), 256, 2 * G1_STAGE>>>(act_u, wh + WOFF3, suph, 128, 64);
    spmm_vec_kernel<64><<<SPMM_BLOCKS, 256>>>(suph, b3, act);

    gemm_hmma_kernel<<<dim3(1, GY), 256, 2 * G1_STAGE>>>(act_u, wh + WOFF4, suph, 64, 40);
    spmm_lsm_kernel<<<SPMM_BLOCKS, 256>>>(suph, b4, out);
}